// round 8
// baseline (speedup 1.0000x reference)
#include <cuda_runtime.h>
#include <math.h>

// Problem dims
#define Bb 4
#define Tt 16
#define Ss 256
#define Dd 512
#define Nn 8
#define Ecols (Dd*Nn)     // 4096
#define Mrows (Bb*Ss)     // 1024
#define Kdim  Dd          // 512

// ---------------- scratch (no allocation allowed -> __device__ globals) ----
// __align__(16): these are accessed through float4* casts; language only
// guarantees 4B alignment for float arrays -> force 16B to avoid err715.
__device__ __align__(16) float g_pop[Mrows * Ecols];  // sigmoid(pop response), [m, e] (16.8 MB)
__device__ __align__(16) float g_rate[Bb*Ss*Dd];
__device__ __align__(16) float g_phase[Bb*Ss*Dd];
__device__ __align__(16) int   g_st[Bb*Ss*Dd];
__device__ float g_w[4];

// ---------------- helpers ----------------
__device__ __forceinline__ float sigf(float x) {
    // numerically stable logistic, matches jax.nn.sigmoid tails
    if (x >= 0.0f) { return 1.0f / (1.0f + expf(-x)); }
    float z = expf(x);
    return z / (1.0f + z);
}

typedef unsigned long long ull;

__device__ __forceinline__ ull dup2(float v) {
    ull r; asm("mov.b64 %0, {%1, %1};" : "=l"(r) : "f"(v)); return r;
}
__device__ __forceinline__ ull fma2(ull a, ull b, ull c) {
    ull d; asm("fma.rn.f32x2 %0, %1, %2, %3;" : "=l"(d) : "l"(a), "l"(b), "l"(c));
    return d;
}
__device__ __forceinline__ float2 up2(ull v) {
    float lo, hi; asm("mov.b64 {%0, %1}, %2;" : "=f"(lo), "=f"(hi) : "l"(v));
    return make_float2(lo, hi);
}

// ---------------- kernel 1: per-(b,s,d) prep + softmax weights ------------
__global__ __launch_bounds__(256) void prep_kernel(
    const float* __restrict__ x,
    const float* __restrict__ noise,
    const float* __restrict__ ew)
{
    int i = blockIdx.x * blockDim.x + threadIdx.x;
    if (i < Bb*Ss*Dd) {
        float s = sigf(x[i]);
        float r = s * 0.9f + 0.05f;
        r = r + noise[i] * 0.1f;
        r = fminf(fmaxf(r, 0.0f), 1.0f);
        g_rate[i]  = r;
        g_st[i]    = (int)(s * 15.0f);          // truncation like .astype(int32)
        g_phase[i] = s * 6.2831855f;            // float(2*pi)
    }
    if (blockIdx.x == 0 && threadIdx.x == 0) {
        float m = fmaxf(fmaxf(ew[0], ew[1]), fmaxf(ew[2], ew[3]));
        float e0 = expf(ew[0]-m), e1 = expf(ew[1]-m), e2 = expf(ew[2]-m), e3 = expf(ew[3]-m);
        float s = e0 + e1 + e2 + e3;
        g_w[0] = e0/s; g_w[1] = e1/s; g_w[2] = e2/s; g_w[3] = e3/s;
    }
}

// ---------------- kernel 2: population GEMM (f32x2 packed FMA) ------------
// C[m,e] = sigmoid( sum_k X[m,k]*W[e,k] + bias[e] ),  X:[1024,512] W:[4096,512]
#define BM 64
#define BN 64
#define BK 16
#define ASTR 66   // ull stride  (padded)
#define BSTR 68   // float stride (padded)

__global__ __launch_bounds__(256) void gemm_pop_kernel(
    const float* __restrict__ X,
    const float* __restrict__ W,
    const float* __restrict__ bias)
{
    __shared__ __align__(16) ull   Ad[BK][ASTR];   // A values duplicated into both f32x2 lanes
    __shared__ __align__(16) float Bsm[BK][BSTR];

    const int tid = threadIdx.x;
    const int tx  = tid & 15;        // n-direction (4 cols each)
    const int ty  = tid >> 4;        // m-direction (4 rows each)
    const int n0  = blockIdx.x * BN;
    const int m0  = blockIdx.y * BM;
    const int row = tid >> 2;        // 0..63 (tile row for loads)
    const int kq  = (tid & 3) * 4;   // 0,4,8,12 (k-quad for loads)

    ull acc[4][2];
    #pragma unroll
    for (int i = 0; i < 4; i++) { acc[i][0] = 0ULL; acc[i][1] = 0ULL; }

    for (int k0 = 0; k0 < Kdim; k0 += BK) {
        float4 av = *(const float4*)&X[(m0 + row) * Kdim + k0 + kq];
        float4 bv = *(const float4*)&W[(n0 + row) * Kdim + k0 + kq];
        Ad[kq+0][row] = dup2(av.x);
        Ad[kq+1][row] = dup2(av.y);
        Ad[kq+2][row] = dup2(av.z);
        Ad[kq+3][row] = dup2(av.w);
        Bsm[kq+0][row] = bv.x;
        Bsm[kq+1][row] = bv.y;
        Bsm[kq+2][row] = bv.z;
        Bsm[kq+3][row] = bv.w;
        __syncthreads();

        #pragma unroll
        for (int k = 0; k < BK; k++) {
            ulonglong2 a0 = *(const ulonglong2*)&Ad[k][ty*4];
            ulonglong2 a1 = *(const ulonglong2*)&Ad[k][ty*4 + 2];
            ulonglong2 b  = *(const ulonglong2*)&Bsm[k][tx*4];  // (e0,e1) (e2,e3) pairs
            acc[0][0] = fma2(a0.x, b.x, acc[0][0]);
            acc[0][1] = fma2(a0.x, b.y, acc[0][1]);
            acc[1][0] = fma2(a0.y, b.x, acc[1][0]);
            acc[1][1] = fma2(a0.y, b.y, acc[1][1]);
            acc[2][0] = fma2(a1.x, b.x, acc[2][0]);
            acc[2][1] = fma2(a1.x, b.y, acc[2][1]);
            acc[3][0] = fma2(a1.y, b.x, acc[3][0]);
            acc[3][1] = fma2(a1.y, b.y, acc[3][1]);
        }
        __syncthreads();
    }

    const int e0 = n0 + tx*4;
    float4 bb = *(const float4*)&bias[e0];
    #pragma unroll
    for (int i = 0; i < 4; i++) {
        int m = m0 + ty*4 + i;
        float2 p0 = up2(acc[i][0]);
        float2 p1 = up2(acc[i][1]);
        float4 o;
        o.x = sigf(p0.x + bb.x);
        o.y = sigf(p0.y + bb.y);
        o.z = sigf(p1.x + bb.z);
        o.w = sigf(p1.y + bb.w);
        *(float4*)&g_pop[m * Ecols + e0] = o;
    }
}

// ---------------- kernel 3: fused streaming combine -----------------------
// out[b,t,s,d] = w0*rate + w1*temporal + w2*population + w3*phase
__global__ __launch_bounds__(256) void fuse_kernel(
    const float* __restrict__ freq,
    const float* __restrict__ rrate,
    const float* __restrict__ rpop,
    float* __restrict__ out)
{
    int idx = blockIdx.x * blockDim.x + threadIdx.x;   // [B,T,S,D] linear
    int d = idx & (Dd - 1);
    int s = (idx >> 9) & (Ss - 1);
    int t = (idx >> 17) & (Tt - 1);
    int b = idx >> 21;
    int bsd = (b * Ss + s) * Dd + d;

    float w0 = g_w[0], w1 = g_w[1], w2 = g_w[2], w3 = g_w[3];

    // rate encoder
    float rs = (rrate[idx] < g_rate[bsd]) ? 1.0f : 0.0f;
    // temporal encoder (one-hot in t)
    float ts = (t == g_st[bsd]) ? 1.0f : 0.0f;
    // population encoder: 8 Bernoulli draws vs pop_rates, averaged
    const float4* rp4 = (const float4*)rpop + (size_t)idx * 2;
    const float4* pr4 = (const float4*)g_pop + (size_t)bsd * 2;
    float4 r0 = rp4[0], r1 = rp4[1];
    float4 p0 = pr4[0], p1 = pr4[1];
    int cnt = (r0.x < p0.x) + (r0.y < p0.y) + (r0.z < p0.z) + (r0.w < p0.w)
            + (r1.x < p1.x) + (r1.y < p1.y) + (r1.z < p1.z) + (r1.w < p1.w);
    float pop = (float)cnt * 0.125f;
    // phase encoder: sin(f_d * t_lin + phase) > 0.5
    const float tstep = 6.2831855f / 15.0f;            // linspace delta in f32
    float wave = sinf(freq[d] * ((float)t * tstep) + g_phase[bsd]);
    float ps = (wave > 0.5f) ? 1.0f : 0.0f;

    out[idx] = w0 * rs + w1 * ts + w2 * pop + w3 * ps;
}

// ---------------- launch ---------------------------------------------------
extern "C" void kernel_launch(void* const* d_in, const int* in_sizes, int n_in,
                              void* d_out, int out_size)
{
    const float* x     = (const float*)d_in[0];  // [B,S,D]
    const float* freq  = (const float*)d_in[1];  // [D]
    const float* pw    = (const float*)d_in[2];  // [D*N, D]
    const float* pb    = (const float*)d_in[3];  // [D*N]
    const float* ew    = (const float*)d_in[4];  // [4]
    const float* noise = (const float*)d_in[5];  // [B,S,D]
    const float* rr    = (const float*)d_in[6];  // [B,T,S,D]
    const float* rp    = (const float*)d_in[7];  // [B,T,S,D,N]
    float* out = (float*)d_out;                  // [B,T,S,D]

    prep_kernel<<<(Bb*Ss*Dd + 255) / 256, 256>>>(x, noise, ew);
    gemm_pop_kernel<<<dim3(Ecols / BN, Mrows / BM), 256>>>(x, pw, pb);
    fuse_kernel<<<(Bb*Tt*Ss*Dd) / 256, 256>>>(freq, rr, rp, out);
}

// round 10
// speedup vs baseline: 1.1240x; 1.1240x over previous
#include <cuda_runtime.h>
#include <cuda_bf16.h>
#include <math.h>
#include <stdint.h>

// Problem dims
#define Bb 4
#define Tt 16
#define Ss 256
#define Dd 512
#define Nn 8
#define Ecols (Dd*Nn)     // 4096
#define Mrows (Bb*Ss)     // 1024
#define Kdim  Dd          // 512
#define KAUG  (3*Kdim)    // 1536 : [hi|hi|lo] x [hi|lo|hi] 3-product split GEMM

typedef unsigned long long ull;

// ---------------- scratch (no allocation allowed -> __device__ globals) ----
__device__ __align__(16) float g_pop[Mrows * Ecols];  // sigmoid(pop response) [m,e] (16.8 MB)
__device__ __align__(16) float g_rate[Bb*Ss*Dd];
__device__ __align__(16) float g_phase[Bb*Ss*Dd];
__device__ __align__(16) int   g_st[Bb*Ss*Dd];
__device__ float g_w[4];
// split-bf16 augmented operands
__device__ __align__(16) __nv_bfloat16 g_xa[Mrows * KAUG];   // 3 MB
__device__ __align__(16) __nv_bfloat16 g_wa[Ecols * KAUG];   // 12.6 MB

// ---------------- helpers ----------------
__device__ __forceinline__ float sigf(float x) {
    if (x >= 0.0f) { return 1.0f / (1.0f + expf(-x)); }
    float z = expf(x);
    return z / (1.0f + z);
}

__device__ __forceinline__ uint32_t smem_u32(const void* p) {
    uint32_t a;
    asm("{ .reg .u64 t; cvta.to.shared.u64 t, %1; cvt.u32.u64 %0, t; }" : "=r"(a) : "l"(p));
    return a;
}

__device__ __forceinline__ void cp16(uint32_t s, const void* g) {
    asm volatile("cp.async.cg.shared.global [%0], [%1], 16;" :: "r"(s), "l"(g) : "memory");
}

#define LDSM4(r, addr) \
    asm volatile("ldmatrix.sync.aligned.m8n8.x4.shared.b16 {%0,%1,%2,%3}, [%4];" \
        : "=r"((r)[0]), "=r"((r)[1]), "=r"((r)[2]), "=r"((r)[3]) : "r"(addr))

#define MMA16816(d, a, b0, b1) \
    asm volatile("mma.sync.aligned.m16n8k16.row.col.f32.bf16.bf16.f32 " \
        "{%0,%1,%2,%3}, {%4,%5,%6,%7}, {%8,%9}, {%0,%1,%2,%3};" \
        : "+f"((d)[0]), "+f"((d)[1]), "+f"((d)[2]), "+f"((d)[3]) \
        : "r"((a)[0]), "r"((a)[1]), "r"((a)[2]), "r"((a)[3]), "r"(b0), "r"(b1))

__device__ __forceinline__ ull pack4_hi(float4 v, float4& lo) {
    __nv_bfloat16 h0 = __float2bfloat16_rn(v.x);
    __nv_bfloat16 h1 = __float2bfloat16_rn(v.y);
    __nv_bfloat16 h2 = __float2bfloat16_rn(v.z);
    __nv_bfloat16 h3 = __float2bfloat16_rn(v.w);
    lo.x = v.x - __bfloat162float(h0);
    lo.y = v.y - __bfloat162float(h1);
    lo.z = v.z - __bfloat162float(h2);
    lo.w = v.w - __bfloat162float(h3);
    __nv_bfloat162 p0; p0.x = h0; p0.y = h1;
    __nv_bfloat162 p1; p1.x = h2; p1.y = h3;
    uint32_t u0 = *(uint32_t*)&p0, u1 = *(uint32_t*)&p1;
    return (ull)u0 | ((ull)u1 << 32);
}
__device__ __forceinline__ ull pack4(float4 v) {
    __nv_bfloat162 p0; p0.x = __float2bfloat16_rn(v.x); p0.y = __float2bfloat16_rn(v.y);
    __nv_bfloat162 p1; p1.x = __float2bfloat16_rn(v.z); p1.y = __float2bfloat16_rn(v.w);
    uint32_t u0 = *(uint32_t*)&p0, u1 = *(uint32_t*)&p1;
    return (ull)u0 | ((ull)u1 << 32);
}

// ---------------- kernel 1: per-(b,s,d) prep + softmax weights ------------
__global__ __launch_bounds__(256) void prep_kernel(
    const float* __restrict__ x,
    const float* __restrict__ noise,
    const float* __restrict__ ew)
{
    int i = blockIdx.x * blockDim.x + threadIdx.x;
    if (i < Bb*Ss*Dd) {
        float s = sigf(x[i]);
        float r = s * 0.9f + 0.05f;
        r = r + noise[i] * 0.1f;
        r = fminf(fmaxf(r, 0.0f), 1.0f);
        g_rate[i]  = r;
        g_st[i]    = (int)(s * 15.0f);
        g_phase[i] = s * 6.2831855f;
    }
    if (blockIdx.x == 0 && threadIdx.x == 0) {
        float m = fmaxf(fmaxf(ew[0], ew[1]), fmaxf(ew[2], ew[3]));
        float e0 = expf(ew[0]-m), e1 = expf(ew[1]-m), e2 = expf(ew[2]-m), e3 = expf(ew[3]-m);
        float s = e0 + e1 + e2 + e3;
        g_w[0] = e0/s; g_w[1] = e1/s; g_w[2] = e2/s; g_w[3] = e3/s;
    }
}

// ---------------- kernel 1b: split fp32 -> bf16 hi/lo augmented operands --
// Xaug row: [Xhi | Xhi | Xlo]   Waug row: [Whi | Wlo | Whi]
__global__ __launch_bounds__(256) void split_x_kernel(const float* __restrict__ X)
{
    int i = blockIdx.x * blockDim.x + threadIdx.x;     // quad id, 1024*128
    int m = i >> 7, kq = (i & 127) << 2;
    float4 v = *(const float4*)&X[m * Kdim + kq];
    float4 lo; ull hi = pack4_hi(v, lo); ull lp = pack4(lo);
    ull* row = (ull*)&g_xa[(size_t)m * KAUG];
    int q = kq >> 2;
    row[q] = hi; row[128 + q] = hi; row[256 + q] = lp;
}
__global__ __launch_bounds__(256) void split_w_kernel(const float* __restrict__ W)
{
    int i = blockIdx.x * blockDim.x + threadIdx.x;     // quad id, 4096*128
    int n = i >> 7, kq = (i & 127) << 2;
    float4 v = *(const float4*)&W[n * Kdim + kq];
    float4 lo; ull hi = pack4_hi(v, lo); ull lp = pack4(lo);
    ull* row = (ull*)&g_wa[(size_t)n * KAUG];
    int q = kq >> 2;
    row[q] = hi; row[128 + q] = lp; row[256 + q] = hi;
}

// ---------------- kernel 2: bf16 mma.sync GEMM, fused sigmoid epilogue ----
// g_pop[m,e] = sigmoid( Xaug[m,:] . Waug[e,:] + bias[e] ),  K' = 1536
#define BM 128
#define BN 128
#define BK 32
#define NKT (KAUG/BK)     // 48
#define TSTR 80           // padded row stride (bytes): 64B data + 16B pad -> conflict-free ldmatrix
#define ATILE (128*TSTR)  // 10240 B per tile buffer

__global__ __launch_bounds__(256) void gemm_mma_kernel(const float* __restrict__ bias)
{
    __shared__ __align__(16) char sm[4 * ATILE];   // A[2], B[2] double buffers (40 KB)
    const uint32_t sbase = smem_u32(sm);
    const int tid = threadIdx.x;
    const int w = tid >> 5, l = tid & 31;
    const int wm = w & 3, wn = w >> 2;             // 4x2 warp grid, warp tile 32x64
    const int m0 = blockIdx.y * BM, n0 = blockIdx.x * BN;

    float acc[2][8][4];
    #pragma unroll
    for (int mt = 0; mt < 2; mt++)
        #pragma unroll
        for (int nt = 0; nt < 8; nt++)
            #pragma unroll
            for (int j = 0; j < 4; j++) acc[mt][nt][j] = 0.0f;

    auto load_stage = [&](int buf, int kt) {
        const int kbase = kt * BK;
        #pragma unroll
        for (int j = 0; j < 2; j++) {
            int c = tid + 256 * j;                 // 512 chunks per tile
            int row = c >> 2, kc = c & 3;
            uint32_t so = (uint32_t)(row * TSTR + kc * 16);
            cp16(sbase + buf * ATILE + so,
                 &g_xa[(size_t)(m0 + row) * KAUG + kbase + kc * 8]);
            cp16(sbase + 2 * ATILE + buf * ATILE + so,
                 &g_wa[(size_t)(n0 + row) * KAUG + kbase + kc * 8]);
        }
        asm volatile("cp.async.commit_group;" ::: "memory");
    };

    load_stage(0, 0);

    const int lr = l & 15, lh = l >> 4;
    for (int kt = 0; kt < NKT; kt++) {
        const int buf = kt & 1;
        if (kt + 1 < NKT) {
            load_stage(buf ^ 1, kt + 1);
            asm volatile("cp.async.wait_group 1;" ::: "memory");
        } else {
            asm volatile("cp.async.wait_group 0;" ::: "memory");
        }
        __syncthreads();

        const uint32_t sa  = sbase + buf * ATILE;
        const uint32_t sbb = sbase + 2 * ATILE + buf * ATILE;
        #pragma unroll
        for (int kk = 0; kk < 2; kk++) {           // two k16 steps per BK=32
            uint32_t a[2][4], b[4][4];
            #pragma unroll
            for (int mt = 0; mt < 2; mt++) {
                uint32_t addr = sa + (uint32_t)((wm*32 + mt*16 + lr) * TSTR + (kk*2 + lh) * 16);
                LDSM4(a[mt], addr);
            }
            #pragma unroll
            for (int np = 0; np < 4; np++) {
                uint32_t addr = sbb + (uint32_t)((wn*64 + np*16 + lr) * TSTR + (kk*2 + lh) * 16);
                LDSM4(b[np], addr);
            }
            #pragma unroll
            for (int mt = 0; mt < 2; mt++)
                #pragma unroll
                for (int np = 0; np < 4; np++) {
                    MMA16816(acc[mt][np*2],     a[mt], b[np][0], b[np][2]);
                    MMA16816(acc[mt][np*2 + 1], a[mt], b[np][1], b[np][3]);
                }
        }
        __syncthreads();
    }

    // epilogue: bias + stable sigmoid, write g_pop
    #pragma unroll
    for (int mt = 0; mt < 2; mt++) {
        int row = m0 + wm*32 + mt*16 + (l >> 2);
        #pragma unroll
        for (int nt = 0; nt < 8; nt++) {
            int col = n0 + wn*64 + nt*8 + 2*(l & 3);
            float2 bb = *(const float2*)&bias[col];
            float2 o0, o1;
            o0.x = sigf(acc[mt][nt][0] + bb.x);
            o0.y = sigf(acc[mt][nt][1] + bb.y);
            o1.x = sigf(acc[mt][nt][2] + bb.x);
            o1.y = sigf(acc[mt][nt][3] + bb.y);
            *(float2*)&g_pop[(size_t)row * Ecols + col] = o0;
            *(float2*)&g_pop[(size_t)(row + 8) * Ecols + col] = o1;
        }
    }
}

// ---------------- kernel 3: fused streaming combine -----------------------
__global__ __launch_bounds__(256) void fuse_kernel(
    const float* __restrict__ freq,
    const float* __restrict__ rrate,
    const float* __restrict__ rpop,
    float* __restrict__ out)
{
    int idx = blockIdx.x * blockDim.x + threadIdx.x;   // [B,T,S,D] linear
    int d = idx & (Dd - 1);
    int s = (idx >> 9) & (Ss - 1);
    int t = (idx >> 17) & (Tt - 1);
    int b = idx >> 21;
    int bsd = (b * Ss + s) * Dd + d;

    float w0 = g_w[0], w1 = g_w[1], w2 = g_w[2], w3 = g_w[3];

    float rs = (rrate[idx] < g_rate[bsd]) ? 1.0f : 0.0f;
    float ts = (t == g_st[bsd]) ? 1.0f : 0.0f;
    const float4* rp4 = (const float4*)rpop + (size_t)idx * 2;
    const float4* pr4 = (const float4*)g_pop + (size_t)bsd * 2;
    float4 r0 = rp4[0], r1 = rp4[1];
    float4 p0 = pr4[0], p1 = pr4[1];
    int cnt = (r0.x < p0.x) + (r0.y < p0.y) + (r0.z < p0.z) + (r0.w < p0.w)
            + (r1.x < p1.x) + (r1.y < p1.y) + (r1.z < p1.z) + (r1.w < p1.w);
    float pop = (float)cnt * 0.125f;
    const float tstep = 6.2831855f / 15.0f;
    float wave = sinf(freq[d] * ((float)t * tstep) + g_phase[bsd]);
    float ps = (wave > 0.5f) ? 1.0f : 0.0f;

    out[idx] = w0 * rs + w1 * ts + w2 * pop + w3 * ps;
}

// ---------------- launch ---------------------------------------------------
extern "C" void kernel_launch(void* const* d_in, const int* in_sizes, int n_in,
                              void* d_out, int out_size)
{
    const float* x     = (const float*)d_in[0];  // [B,S,D]
    const float* freq  = (const float*)d_in[1];  // [D]
    const float* pw    = (const float*)d_in[2];  // [D*N, D]
    const float* pb    = (const float*)d_in[3];  // [D*N]
    const float* ew    = (const float*)d_in[4];  // [4]
    const float* noise = (const float*)d_in[5];  // [B,S,D]
    const float* rr    = (const float*)d_in[6];  // [B,T,S,D]
    const float* rp    = (const float*)d_in[7];  // [B,T,S,D,N]
    float* out = (float*)d_out;                  // [B,T,S,D]

    prep_kernel<<<(Bb*Ss*Dd + 255) / 256, 256>>>(x, noise, ew);
    split_x_kernel<<<(Mrows*Kdim/4) / 256, 256>>>(x);
    split_w_kernel<<<(Ecols*Kdim/4) / 256, 256>>>(pw);
    gemm_mma_kernel<<<dim3(Ecols / BN, Mrows / BM), 256>>>(pb);
    fuse_kernel<<<(Bb*Tt*Ss*Dd) / 256, 256>>>(freq, rr, rp, out);
}

// round 11
// speedup vs baseline: 1.6985x; 1.5110x over previous
#include <cuda_runtime.h>
#include <cuda_bf16.h>
#include <math.h>
#include <stdint.h>

// Problem dims
#define Bb 4
#define Tt 16
#define Ss 256
#define Dd 512
#define Nn 8
#define Ecols (Dd*Nn)     // 4096
#define Mrows (Bb*Ss)     // 1024
#define Kdim  Dd          // 512
#define KAUG  (3*Kdim)    // 1536 : [hi|hi|lo] x [hi|lo|hi] 3-product split GEMM

typedef unsigned long long ull;

// ---------------- scratch (no allocation allowed -> __device__ globals) ----
__device__ __align__(16) float g_pop[Mrows * Ecols];  // sigmoid(pop response) [m,e] (16.8 MB)
__device__ __align__(16) float g_rate[Bb*Ss*Dd];
__device__ __align__(16) float g_phase[Bb*Ss*Dd];
__device__ __align__(16) int   g_st[Bb*Ss*Dd];
__device__ float g_w[4];
// split-bf16 augmented operands
__device__ __align__(16) __nv_bfloat16 g_xa[Mrows * KAUG];   // 3 MB
__device__ __align__(16) __nv_bfloat16 g_wa[Ecols * KAUG];   // 12.6 MB

// ---------------- helpers ----------------
__device__ __forceinline__ float sigf(float x) {
    if (x >= 0.0f) { return 1.0f / (1.0f + expf(-x)); }
    float z = expf(x);
    return z / (1.0f + z);
}

__device__ __forceinline__ uint32_t smem_u32(const void* p) {
    uint32_t a;
    asm("{ .reg .u64 t; cvta.to.shared.u64 t, %1; cvt.u32.u64 %0, t; }" : "=r"(a) : "l"(p));
    return a;
}

__device__ __forceinline__ void cp16(uint32_t s, const void* g) {
    asm volatile("cp.async.cg.shared.global [%0], [%1], 16;" :: "r"(s), "l"(g) : "memory");
}

#define LDSM4(r, addr) \
    asm volatile("ldmatrix.sync.aligned.m8n8.x4.shared.b16 {%0,%1,%2,%3}, [%4];" \
        : "=r"((r)[0]), "=r"((r)[1]), "=r"((r)[2]), "=r"((r)[3]) : "r"(addr))

#define MMA16816(d, a, b0, b1) \
    asm volatile("mma.sync.aligned.m16n8k16.row.col.f32.bf16.bf16.f32 " \
        "{%0,%1,%2,%3}, {%4,%5,%6,%7}, {%8,%9}, {%0,%1,%2,%3};" \
        : "+f"((d)[0]), "+f"((d)[1]), "+f"((d)[2]), "+f"((d)[3]) \
        : "r"((a)[0]), "r"((a)[1]), "r"((a)[2]), "r"((a)[3]), "r"(b0), "r"(b1))

__device__ __forceinline__ ull pack4_hi(float4 v, float4& lo) {
    __nv_bfloat16 h0 = __float2bfloat16_rn(v.x);
    __nv_bfloat16 h1 = __float2bfloat16_rn(v.y);
    __nv_bfloat16 h2 = __float2bfloat16_rn(v.z);
    __nv_bfloat16 h3 = __float2bfloat16_rn(v.w);
    lo.x = v.x - __bfloat162float(h0);
    lo.y = v.y - __bfloat162float(h1);
    lo.z = v.z - __bfloat162float(h2);
    lo.w = v.w - __bfloat162float(h3);
    __nv_bfloat162 p0; p0.x = h0; p0.y = h1;
    __nv_bfloat162 p1; p1.x = h2; p1.y = h3;
    uint32_t u0 = *(uint32_t*)&p0, u1 = *(uint32_t*)&p1;
    return (ull)u0 | ((ull)u1 << 32);
}
__device__ __forceinline__ ull pack4(float4 v) {
    __nv_bfloat162 p0; p0.x = __float2bfloat16_rn(v.x); p0.y = __float2bfloat16_rn(v.y);
    __nv_bfloat162 p1; p1.x = __float2bfloat16_rn(v.z); p1.y = __float2bfloat16_rn(v.w);
    uint32_t u0 = *(uint32_t*)&p0, u1 = *(uint32_t*)&p1;
    return (ull)u0 | ((ull)u1 << 32);
}

// ---------------- kernel 1: per-(b,s,d) prep + softmax weights ------------
__global__ __launch_bounds__(256) void prep_kernel(
    const float* __restrict__ x,
    const float* __restrict__ noise,
    const float* __restrict__ ew)
{
    int i = blockIdx.x * blockDim.x + threadIdx.x;
    if (i < Bb*Ss*Dd) {
        float s = sigf(x[i]);
        float r = s * 0.9f + 0.05f;
        r = r + noise[i] * 0.1f;
        r = fminf(fmaxf(r, 0.0f), 1.0f);
        g_rate[i]  = r;
        g_st[i]    = (int)(s * 15.0f);
        g_phase[i] = s * 6.2831855f;
    }
    if (blockIdx.x == 0 && threadIdx.x == 0) {
        float m = fmaxf(fmaxf(ew[0], ew[1]), fmaxf(ew[2], ew[3]));
        float e0 = expf(ew[0]-m), e1 = expf(ew[1]-m), e2 = expf(ew[2]-m), e3 = expf(ew[3]-m);
        float s = e0 + e1 + e2 + e3;
        g_w[0] = e0/s; g_w[1] = e1/s; g_w[2] = e2/s; g_w[3] = e3/s;
    }
}

// ---------------- kernel 1b: split fp32 -> bf16 hi/lo augmented operands --
// Xaug row: [Xhi | Xhi | Xlo]   Waug row: [Whi | Wlo | Whi]
__global__ __launch_bounds__(256) void split_x_kernel(const float* __restrict__ X)
{
    int i = blockIdx.x * blockDim.x + threadIdx.x;     // quad id, 1024*128
    int m = i >> 7, kq = (i & 127) << 2;
    float4 v = *(const float4*)&X[m * Kdim + kq];
    float4 lo; ull hi = pack4_hi(v, lo); ull lp = pack4(lo);
    ull* row = (ull*)&g_xa[(size_t)m * KAUG];
    int q = kq >> 2;
    row[q] = hi; row[128 + q] = hi; row[256 + q] = lp;
}
__global__ __launch_bounds__(256) void split_w_kernel(const float* __restrict__ W)
{
    int i = blockIdx.x * blockDim.x + threadIdx.x;     // quad id, 4096*128
    int n = i >> 7, kq = (i & 127) << 2;
    float4 v = *(const float4*)&W[n * Kdim + kq];
    float4 lo; ull hi = pack4_hi(v, lo); ull lp = pack4(lo);
    ull* row = (ull*)&g_wa[(size_t)n * KAUG];
    int q = kq >> 2;
    row[q] = hi; row[128 + q] = lp; row[256 + q] = hi;
}

// ---------------- kernel 2: bf16 mma.sync GEMM, fused sigmoid epilogue ----
// g_pop[m,e] = sigmoid( Xaug[m,:] . Waug[e,:] + bias[e] ),  K' = 1536
// BK=64, 2-stage cp.async double buffer, ONE __syncthreads per iteration,
// __launch_bounds__(256,2) + 72KB dyn smem -> 2 CTAs/SM -> all 256 CTAs in 1 wave.
#define BM 128
#define BN 128
#define BK2 64
#define NKT2 (KAUG/BK2)      // 24
#define TSTR2 144            // 128B data + 16B pad: 36 words/row, 36 mod 32 = 4 -> conflict-free ldmatrix
#define ATILE2 (128*TSTR2)   // 18432 B per tile buffer
#define SMEM_GEMM (4*ATILE2) // 73728 B : A[2] + B[2]

__global__ __launch_bounds__(256, 2) void gemm_mma_kernel(const float* __restrict__ bias)
{
    extern __shared__ __align__(16) char sm_dyn[];
    const uint32_t sbase = smem_u32(sm_dyn);
    const int tid = threadIdx.x;
    const int w = tid >> 5, l = tid & 31;
    const int wm = w & 3, wn = w >> 2;             // 4x2 warp grid, warp tile 32x64
    const int m0 = blockIdx.y * BM, n0 = blockIdx.x * BN;

    float acc[2][8][4];
    #pragma unroll
    for (int mt = 0; mt < 2; mt++)
        #pragma unroll
        for (int nt = 0; nt < 8; nt++)
            #pragma unroll
            for (int j = 0; j < 4; j++) acc[mt][nt][j] = 0.0f;

    // hoisted ldmatrix base offsets (per-warp constant)
    const int lr = l & 15, lh = l >> 4;
    uint32_t aoff[2], boff[4];
    #pragma unroll
    for (int mt = 0; mt < 2; mt++) aoff[mt] = (uint32_t)((wm*32 + mt*16 + lr) * TSTR2 + lh*16);
    #pragma unroll
    for (int np = 0; np < 4; np++) boff[np] = (uint32_t)((wn*64 + np*16 + lr) * TSTR2 + lh*16);

    auto load_stage = [&](int buf, int kt) {
        const int kb = kt * BK2;
        const uint32_t sA = sbase + (uint32_t)(buf * ATILE2);
        const uint32_t sB = sbase + (uint32_t)(2*ATILE2 + buf * ATILE2);
        #pragma unroll
        for (int j = 0; j < 4; j++) {
            int c = tid + 256 * j;                 // 1024 16B-chunks per tile
            int row = c >> 3, kc = c & 7;
            uint32_t so = (uint32_t)(row * TSTR2 + kc * 16);
            cp16(sA + so, &g_xa[(size_t)(m0 + row) * KAUG + kb + kc * 8]);
            cp16(sB + so, &g_wa[(size_t)(n0 + row) * KAUG + kb + kc * 8]);
        }
        asm volatile("cp.async.commit_group;" ::: "memory");
    };

    load_stage(0, 0);

    for (int kt = 0; kt < NKT2; kt++) {
        const int buf = kt & 1;
        asm volatile("cp.async.wait_group 0;" ::: "memory");
        __syncthreads();   // stage kt visible to all; all warps done reading buf^1 (iter kt-1)
        if (kt + 1 < NKT2) load_stage(buf ^ 1, kt + 1);   // overlaps compute below

        const uint32_t sA = sbase + (uint32_t)(buf * ATILE2);
        const uint32_t sB = sbase + (uint32_t)(2*ATILE2 + buf * ATILE2);
        #pragma unroll
        for (int kk = 0; kk < 4; kk++) {           // four k16 steps per BK=64
            uint32_t a[2][4], b[4][4];
            #pragma unroll
            for (int mt = 0; mt < 2; mt++) LDSM4(a[mt], sA + aoff[mt] + kk*32);
            #pragma unroll
            for (int np = 0; np < 4; np++) LDSM4(b[np], sB + boff[np] + kk*32);
            #pragma unroll
            for (int mt = 0; mt < 2; mt++)
                #pragma unroll
                for (int np = 0; np < 4; np++) {
                    MMA16816(acc[mt][np*2],     a[mt], b[np][0], b[np][2]);
                    MMA16816(acc[mt][np*2 + 1], a[mt], b[np][1], b[np][3]);
                }
        }
    }

    // epilogue: bias + stable sigmoid, write g_pop
    #pragma unroll
    for (int mt = 0; mt < 2; mt++) {
        int row = m0 + wm*32 + mt*16 + (l >> 2);
        #pragma unroll
        for (int nt = 0; nt < 8; nt++) {
            int col = n0 + wn*64 + nt*8 + 2*(l & 3);
            float2 bb = *(const float2*)&bias[col];
            float2 o0, o1;
            o0.x = sigf(acc[mt][nt][0] + bb.x);
            o0.y = sigf(acc[mt][nt][1] + bb.y);
            o1.x = sigf(acc[mt][nt][2] + bb.x);
            o1.y = sigf(acc[mt][nt][3] + bb.y);
            *(float2*)&g_pop[(size_t)row * Ecols + col] = o0;
            *(float2*)&g_pop[(size_t)(row + 8) * Ecols + col] = o1;
        }
    }
}

// ---------------- kernel 3: fused streaming combine (t-paired) ------------
// Each thread handles (b, t, s, d) and (b, t+8, s, d): halves g_pop/L2 and
// per-(b,s,d) scalar traffic, doubles MLP on the compulsory rand_pop stream.
__global__ __launch_bounds__(256) void fuse_kernel(
    const float* __restrict__ freq,
    const float* __restrict__ rrate,
    const float* __restrict__ rpop,
    float* __restrict__ out)
{
    int idx = blockIdx.x * blockDim.x + threadIdx.x;   // [B, 8, S, D] linear
    int d  = idx & (Dd - 1);
    int s  = (idx >> 9) & (Ss - 1);
    int th = (idx >> 17) & 7;        // t half: handles t=th and t=th+8
    int b  = idx >> 20;
    int bsd = (b * Ss + s) * Dd + d;
    int i0 = ((b * Tt + th) * Ss + s) * Dd + d;
    int i1 = i0 + 8 * Ss * Dd;

    float w0 = g_w[0], w1 = g_w[1], w2 = g_w[2], w3 = g_w[3];

    float rate  = g_rate[bsd];
    int   st    = g_st[bsd];
    float phase = g_phase[bsd];
    float fd    = freq[d];

    const float4* pr4 = (const float4*)g_pop + (size_t)bsd * 2;
    float4 p0 = pr4[0], p1 = pr4[1];

    const float4* ra = (const float4*)rpop + (size_t)i0 * 2;
    const float4* rb = (const float4*)rpop + (size_t)i1 * 2;
    float4 a0 = ra[0], a1 = ra[1];
    float4 b0 = rb[0], b1 = rb[1];
    float rr0 = rrate[i0], rr1 = rrate[i1];

    int cnt0 = (a0.x < p0.x) + (a0.y < p0.y) + (a0.z < p0.z) + (a0.w < p0.w)
             + (a1.x < p1.x) + (a1.y < p1.y) + (a1.z < p1.z) + (a1.w < p1.w);
    int cnt1 = (b0.x < p0.x) + (b0.y < p0.y) + (b0.z < p0.z) + (b0.w < p0.w)
             + (b1.x < p1.x) + (b1.y < p1.y) + (b1.z < p1.z) + (b1.w < p1.w);

    const float tstep = 6.2831855f / 15.0f;
    float wv0 = sinf(fd * ((float)th * tstep) + phase);
    float wv1 = sinf(fd * ((float)(th + 8) * tstep) + phase);

    float o0 = w0 * ((rr0 < rate) ? 1.0f : 0.0f)
             + w1 * ((th == st) ? 1.0f : 0.0f)
             + w2 * ((float)cnt0 * 0.125f)
             + w3 * ((wv0 > 0.5f) ? 1.0f : 0.0f);
    float o1 = w0 * ((rr1 < rate) ? 1.0f : 0.0f)
             + w1 * ((th + 8 == st) ? 1.0f : 0.0f)
             + w2 * ((float)cnt1 * 0.125f)
             + w3 * ((wv1 > 0.5f) ? 1.0f : 0.0f);

    out[i0] = o0;
    out[i1] = o1;
}

// ---------------- launch ---------------------------------------------------
extern "C" void kernel_launch(void* const* d_in, const int* in_sizes, int n_in,
                              void* d_out, int out_size)
{
    const float* x     = (const float*)d_in[0];  // [B,S,D]
    const float* freq  = (const float*)d_in[1];  // [D]
    const float* pw    = (const float*)d_in[2];  // [D*N, D]
    const float* pb    = (const float*)d_in[3];  // [D*N]
    const float* ew    = (const float*)d_in[4];  // [4]
    const float* noise = (const float*)d_in[5];  // [B,S,D]
    const float* rr    = (const float*)d_in[6];  // [B,T,S,D]
    const float* rp    = (const float*)d_in[7];  // [B,T,S,D,N]
    float* out = (float*)d_out;                  // [B,T,S,D]

    cudaFuncSetAttribute(gemm_mma_kernel,
                         cudaFuncAttributeMaxDynamicSharedMemorySize, SMEM_GEMM);

    prep_kernel<<<(Bb*Ss*Dd + 255) / 256, 256>>>(x, noise, ew);
    split_x_kernel<<<(Mrows*Kdim/4) / 256, 256>>>(x);
    split_w_kernel<<<(Ecols*Kdim/4) / 256, 256>>>(pw);
    gemm_mma_kernel<<<dim3(Ecols / BN, Mrows / BM), 256, SMEM_GEMM>>>(pb);
    fuse_kernel<<<(Bb*(Tt/2)*Ss*Dd) / 256, 256>>>(freq, rr, rp, out);
}

// round 12
// speedup vs baseline: 1.7034x; 1.0029x over previous
#include <cuda_runtime.h>
#include <cuda_bf16.h>
#include <math.h>
#include <stdint.h>

// Problem dims
#define Bb 4
#define Tt 16
#define Ss 256
#define Dd 512
#define Nn 8
#define Ecols (Dd*Nn)     // 4096
#define Mrows (Bb*Ss)     // 1024
#define Kdim  Dd          // 512
#define KAUG  (3*Kdim)    // 1536 : [hi|hi|lo] x [hi|lo|hi] 3-product split GEMM

typedef unsigned long long ull;

// ---------------- scratch (no allocation allowed -> __device__ globals) ----
__device__ __align__(16) float g_pop[Mrows * Ecols];  // sigmoid(pop response) [m,e] (16.8 MB)
__device__ __align__(16) float g_rate[Bb*Ss*Dd];
__device__ __align__(16) float g_phase[Bb*Ss*Dd];
__device__ __align__(16) int   g_st[Bb*Ss*Dd];
__device__ float g_w[4];
// split-bf16 augmented operands
__device__ __align__(16) __nv_bfloat16 g_xa[Mrows * KAUG];   // 3 MB
__device__ __align__(16) __nv_bfloat16 g_wa[Ecols * KAUG];   // 12.6 MB

// ---------------- helpers ----------------
__device__ __forceinline__ float sigf(float x) {
    if (x >= 0.0f) { return 1.0f / (1.0f + expf(-x)); }
    float z = expf(x);
    return z / (1.0f + z);
}

__device__ __forceinline__ uint32_t smem_u32(const void* p) {
    uint32_t a;
    asm("{ .reg .u64 t; cvta.to.shared.u64 t, %1; cvt.u32.u64 %0, t; }" : "=r"(a) : "l"(p));
    return a;
}

__device__ __forceinline__ void cp16(uint32_t s, const void* g) {
    asm volatile("cp.async.cg.shared.global [%0], [%1], 16;" :: "r"(s), "l"(g) : "memory");
}

#define LDSM4(r, addr) \
    asm volatile("ldmatrix.sync.aligned.m8n8.x4.shared.b16 {%0,%1,%2,%3}, [%4];" \
        : "=r"((r)[0]), "=r"((r)[1]), "=r"((r)[2]), "=r"((r)[3]) : "r"(addr))

#define MMA16816(d, a, b0, b1) \
    asm volatile("mma.sync.aligned.m16n8k16.row.col.f32.bf16.bf16.f32 " \
        "{%0,%1,%2,%3}, {%4,%5,%6,%7}, {%8,%9}, {%0,%1,%2,%3};" \
        : "+f"((d)[0]), "+f"((d)[1]), "+f"((d)[2]), "+f"((d)[3]) \
        : "r"((a)[0]), "r"((a)[1]), "r"((a)[2]), "r"((a)[3]), "r"(b0), "r"(b1))

__device__ __forceinline__ ull pack4_hi(float4 v, float4& lo) {
    __nv_bfloat16 h0 = __float2bfloat16_rn(v.x);
    __nv_bfloat16 h1 = __float2bfloat16_rn(v.y);
    __nv_bfloat16 h2 = __float2bfloat16_rn(v.z);
    __nv_bfloat16 h3 = __float2bfloat16_rn(v.w);
    lo.x = v.x - __bfloat162float(h0);
    lo.y = v.y - __bfloat162float(h1);
    lo.z = v.z - __bfloat162float(h2);
    lo.w = v.w - __bfloat162float(h3);
    __nv_bfloat162 p0; p0.x = h0; p0.y = h1;
    __nv_bfloat162 p1; p1.x = h2; p1.y = h3;
    uint32_t u0 = *(uint32_t*)&p0, u1 = *(uint32_t*)&p1;
    return (ull)u0 | ((ull)u1 << 32);
}
__device__ __forceinline__ ull pack4(float4 v) {
    __nv_bfloat162 p0; p0.x = __float2bfloat16_rn(v.x); p0.y = __float2bfloat16_rn(v.y);
    __nv_bfloat162 p1; p1.x = __float2bfloat16_rn(v.z); p1.y = __float2bfloat16_rn(v.w);
    uint32_t u0 = *(uint32_t*)&p0, u1 = *(uint32_t*)&p1;
    return (ull)u0 | ((ull)u1 << 32);
}

// ---------------- kernel 1: per-(b,s,d) prep + softmax weights ------------
__global__ __launch_bounds__(256) void prep_kernel(
    const float* __restrict__ x,
    const float* __restrict__ noise,
    const float* __restrict__ ew)
{
    int i = blockIdx.x * blockDim.x + threadIdx.x;
    if (i < Bb*Ss*Dd) {
        float s = sigf(x[i]);
        float r = s * 0.9f + 0.05f;
        r = r + noise[i] * 0.1f;
        r = fminf(fmaxf(r, 0.0f), 1.0f);
        g_rate[i]  = r;
        g_st[i]    = (int)(s * 15.0f);
        g_phase[i] = s * 6.2831855f;
    }
    if (blockIdx.x == 0 && threadIdx.x == 0) {
        float m = fmaxf(fmaxf(ew[0], ew[1]), fmaxf(ew[2], ew[3]));
        float e0 = expf(ew[0]-m), e1 = expf(ew[1]-m), e2 = expf(ew[2]-m), e3 = expf(ew[3]-m);
        float s = e0 + e1 + e2 + e3;
        g_w[0] = e0/s; g_w[1] = e1/s; g_w[2] = e2/s; g_w[3] = e3/s;
    }
}

// ---------------- kernel 1b: split fp32 -> bf16 hi/lo augmented operands --
// Xaug row: [Xhi | Xhi | Xlo]   Waug row: [Whi | Wlo | Whi]
__global__ __launch_bounds__(256) void split_x_kernel(const float* __restrict__ X)
{
    int i = blockIdx.x * blockDim.x + threadIdx.x;     // quad id, 1024*128
    int m = i >> 7, kq = (i & 127) << 2;
    float4 v = *(const float4*)&X[m * Kdim + kq];
    float4 lo; ull hi = pack4_hi(v, lo); ull lp = pack4(lo);
    ull* row = (ull*)&g_xa[(size_t)m * KAUG];
    int q = kq >> 2;
    row[q] = hi; row[128 + q] = hi; row[256 + q] = lp;
}
__global__ __launch_bounds__(256) void split_w_kernel(const float* __restrict__ W)
{
    int i = blockIdx.x * blockDim.x + threadIdx.x;     // quad id, 4096*128
    int n = i >> 7, kq = (i & 127) << 2;
    float4 v = *(const float4*)&W[n * Kdim + kq];
    float4 lo; ull hi = pack4_hi(v, lo); ull lp = pack4(lo);
    ull* row = (ull*)&g_wa[(size_t)n * KAUG];
    int q = kq >> 2;
    row[q] = hi; row[128 + q] = lp; row[256 + q] = hi;
}

// ---------------- kernel 2: bf16 mma.sync GEMM, fused sigmoid epilogue ----
// g_pop[m,e] = sigmoid( Xaug[m,:] . Waug[e,:] + bias[e] ),  K' = 1536
// BK=64, THREE-stage cp.async pipeline (wait_group 1 in steady state ->
// each load gets ~2 compute iterations of slack), incremental global
// pointers (no per-iter IMAD chains), one __syncthreads per iteration.
// 2 CTAs/SM (reg-capped), smem 3*36864 = 110592 B -> 216KB/SM, fits.
#define BM 128
#define BN 128
#define BK2 64
#define NKT2 (KAUG/BK2)      // 24
#define TSTR2 144            // 128B data + 16B pad: 36 words/row, 36 mod 32 = 4 -> conflict-free ldmatrix
#define ATILE2 (128*TSTR2)   // 18432 B per tile
#define STAGE2 (2*ATILE2)    // A+B per stage = 36864 B
#define SMEM_GEMM (3*STAGE2) // 110592 B

__global__ __launch_bounds__(256, 2) void gemm_mma_kernel(const float* __restrict__ bias)
{
    extern __shared__ __align__(16) char sm_dyn[];
    const uint32_t sbase = smem_u32(sm_dyn);
    const int tid = threadIdx.x;
    const int w = tid >> 5, l = tid & 31;
    const int wm = w & 3, wn = w >> 2;             // 4x2 warp grid, warp tile 32x64
    const int m0 = blockIdx.y * BM, n0 = blockIdx.x * BN;

    float acc[2][8][4];
    #pragma unroll
    for (int mt = 0; mt < 2; mt++)
        #pragma unroll
        for (int nt = 0; nt < 8; nt++)
            #pragma unroll
            for (int j = 0; j < 4; j++) acc[mt][nt][j] = 0.0f;

    // hoisted ldmatrix base offsets (per-warp constant)
    const int lr = l & 15, lh = l >> 4;
    uint32_t aoff[2], boff[4];
    #pragma unroll
    for (int mt = 0; mt < 2; mt++) aoff[mt] = (uint32_t)((wm*32 + mt*16 + lr) * TSTR2 + lh*16);
    #pragma unroll
    for (int np = 0; np < 4; np++) boff[np] = (uint32_t)((wn*64 + np*16 + lr) * TSTR2 + lh*16);

    // incremental global pointers: thread's chunk = row (tid>>3), kc (tid&7)
    // j-step (+32 rows): global +32*KAUG*2 = 98304 B ; smem +32*TSTR2 = 4608 B
    const int trow = tid >> 3, tkc = tid & 7;
    const char* gA = (const char*)g_xa + ((size_t)(m0 + trow) * KAUG + tkc * 8) * 2;
    const char* gB = (const char*)g_wa + ((size_t)(n0 + trow) * KAUG + tkc * 8) * 2;
    const uint32_t so = (uint32_t)(trow * TSTR2 + tkc * 16);

    auto load_stage = [&](int buf) {
        const uint32_t sA = sbase + (uint32_t)(buf * STAGE2) + so;
        const uint32_t sB = sA + ATILE2;
        #pragma unroll
        for (int j = 0; j < 4; j++) {
            cp16(sA + j * 4608u, gA + j * 98304);
            cp16(sB + j * 4608u, gB + j * 98304);
        }
        asm volatile("cp.async.commit_group;" ::: "memory");
        gA += 128;  // advance one BK2 stage (64 bf16)
        gB += 128;
    };

    load_stage(0);
    load_stage(1);

    int buf = 0, lb = 2;
    for (int kt = 0; kt < NKT2; kt++) {
        if (kt < NKT2 - 1) {
            asm volatile("cp.async.wait_group 1;" ::: "memory");
        } else {
            asm volatile("cp.async.wait_group 0;" ::: "memory");
        }
        __syncthreads();   // stage kt visible; all warps done with compute kt-1
        if (kt + 2 < NKT2) {
            load_stage(lb);               // overlaps compute below, ~2 iters slack
            lb = (lb == 2) ? 0 : lb + 1;
        }

        const uint32_t sA = sbase + (uint32_t)(buf * STAGE2);
        const uint32_t sB = sA + ATILE2;
        #pragma unroll
        for (int kk = 0; kk < 4; kk++) {           // four k16 steps per BK=64
            uint32_t a[2][4], b[4][4];
            #pragma unroll
            for (int mt = 0; mt < 2; mt++) LDSM4(a[mt], sA + aoff[mt] + kk*32);
            #pragma unroll
            for (int np = 0; np < 4; np++) LDSM4(b[np], sB + boff[np] + kk*32);
            #pragma unroll
            for (int mt = 0; mt < 2; mt++)
                #pragma unroll
                for (int np = 0; np < 4; np++) {
                    MMA16816(acc[mt][np*2],     a[mt], b[np][0], b[np][2]);
                    MMA16816(acc[mt][np*2 + 1], a[mt], b[np][1], b[np][3]);
                }
        }
        buf = (buf == 2) ? 0 : buf + 1;
    }

    // epilogue: bias + stable sigmoid, write g_pop
    #pragma unroll
    for (int mt = 0; mt < 2; mt++) {
        int row = m0 + wm*32 + mt*16 + (l >> 2);
        #pragma unroll
        for (int nt = 0; nt < 8; nt++) {
            int col = n0 + wn*64 + nt*8 + 2*(l & 3);
            float2 bb = *(const float2*)&bias[col];
            float2 o0, o1;
            o0.x = sigf(acc[mt][nt][0] + bb.x);
            o0.y = sigf(acc[mt][nt][1] + bb.y);
            o1.x = sigf(acc[mt][nt][2] + bb.x);
            o1.y = sigf(acc[mt][nt][3] + bb.y);
            *(float2*)&g_pop[(size_t)row * Ecols + col] = o0;
            *(float2*)&g_pop[(size_t)(row + 8) * Ecols + col] = o1;
        }
    }
}

// ---------------- kernel 3: fused streaming combine (t-paired) ------------
__global__ __launch_bounds__(256) void fuse_kernel(
    const float* __restrict__ freq,
    const float* __restrict__ rrate,
    const float* __restrict__ rpop,
    float* __restrict__ out)
{
    int idx = blockIdx.x * blockDim.x + threadIdx.x;   // [B, 8, S, D] linear
    int d  = idx & (Dd - 1);
    int s  = (idx >> 9) & (Ss - 1);
    int th = (idx >> 17) & 7;        // t half: handles t=th and t=th+8
    int b  = idx >> 20;
    int bsd = (b * Ss + s) * Dd + d;
    int i0 = ((b * Tt + th) * Ss + s) * Dd + d;
    int i1 = i0 + 8 * Ss * Dd;

    float w0 = g_w[0], w1 = g_w[1], w2 = g_w[2], w3 = g_w[3];

    float rate  = g_rate[bsd];
    int   st    = g_st[bsd];
    float phase = g_phase[bsd];
    float fd    = freq[d];

    const float4* pr4 = (const float4*)g_pop + (size_t)bsd * 2;
    float4 p0 = pr4[0], p1 = pr4[1];

    const float4* ra = (const float4*)rpop + (size_t)i0 * 2;
    const float4* rb = (const float4*)rpop + (size_t)i1 * 2;
    float4 a0 = ra[0], a1 = ra[1];
    float4 b0 = rb[0], b1 = rb[1];
    float rr0 = rrate[i0], rr1 = rrate[i1];

    int cnt0 = (a0.x < p0.x) + (a0.y < p0.y) + (a0.z < p0.z) + (a0.w < p0.w)
             + (a1.x < p1.x) + (a1.y < p1.y) + (a1.z < p1.z) + (a1.w < p1.w);
    int cnt1 = (b0.x < p0.x) + (b0.y < p0.y) + (b0.z < p0.z) + (b0.w < p0.w)
             + (b1.x < p1.x) + (b1.y < p1.y) + (b1.z < p1.z) + (b1.w < p1.w);

    const float tstep = 6.2831855f / 15.0f;
    float wv0 = sinf(fd * ((float)th * tstep) + phase);
    float wv1 = sinf(fd * ((float)(th + 8) * tstep) + phase);

    float o0 = w0 * ((rr0 < rate) ? 1.0f : 0.0f)
             + w1 * ((th == st) ? 1.0f : 0.0f)
             + w2 * ((float)cnt0 * 0.125f)
             + w3 * ((wv0 > 0.5f) ? 1.0f : 0.0f);
    float o1 = w0 * ((rr1 < rate) ? 1.0f : 0.0f)
             + w1 * ((th + 8 == st) ? 1.0f : 0.0f)
             + w2 * ((float)cnt1 * 0.125f)
             + w3 * ((wv1 > 0.5f) ? 1.0f : 0.0f);

    out[i0] = o0;
    out[i1] = o1;
}

// ---------------- launch ---------------------------------------------------
extern "C" void kernel_launch(void* const* d_in, const int* in_sizes, int n_in,
                              void* d_out, int out_size)
{
    const float* x     = (const float*)d_in[0];  // [B,S,D]
    const float* freq  = (const float*)d_in[1];  // [D]
    const float* pw    = (const float*)d_in[2];  // [D*N, D]
    const float* pb    = (const float*)d_in[3];  // [D*N]
    const float* ew    = (const float*)d_in[4];  // [4]
    const float* noise = (const float*)d_in[5];  // [B,S,D]
    const float* rr    = (const float*)d_in[6];  // [B,T,S,D]
    const float* rp    = (const float*)d_in[7];  // [B,T,S,D,N]
    float* out = (float*)d_out;                  // [B,T,S,D]

    cudaFuncSetAttribute(gemm_mma_kernel,
                         cudaFuncAttributeMaxDynamicSharedMemorySize, SMEM_GEMM);

    prep_kernel<<<(Bb*Ss*Dd + 255) / 256, 256>>>(x, noise, ew);
    split_x_kernel<<<(Mrows*Kdim/4) / 256, 256>>>(x);
    split_w_kernel<<<(Ecols*Kdim/4) / 256, 256>>>(pw);
    gemm_mma_kernel<<<dim3(Ecols / BN, Mrows / BM), 256, SMEM_GEMM>>>(pb);
    fuse_kernel<<<(Bb*(Tt/2)*Ss*Dd) / 256, 256>>>(freq, rr, rp, out);
}